// round 3
// baseline (speedup 1.0000x reference)
#include <cuda_runtime.h>
#include <cuda_bf16.h>

#define N_NODES 100000
#define N_EDGES 1600000
#define IN_FT   128
#define OUT_FT  32

// Scratch for the dense projection result (12.8 MB). Device global: no allocs.
__device__ float g_support[(size_t)N_NODES * OUT_FT];

// ---------------------------------------------------------------------------
// Kernel 1: support = seq @ W.   One warp per node; W lives in smem.
// Each lane holds 4 consecutive seq values (float4), broadcast via shfl.
// Lane l computes output feature l (OUT_FT == 32 == warp size).
// ---------------------------------------------------------------------------
__global__ void gcn_gemm_kernel(const float* __restrict__ seq,
                                const float* __restrict__ W) {
    __shared__ float Wsm[IN_FT * OUT_FT];   // 16 KB
    for (int i = threadIdx.x; i < IN_FT * OUT_FT; i += blockDim.x)
        Wsm[i] = W[i];
    __syncthreads();

    int warp = (blockIdx.x * blockDim.x + threadIdx.x) >> 5;
    int lane = threadIdx.x & 31;
    if (warp >= N_NODES) return;

    // 32 lanes x float4 = 128 floats = full input row, coalesced 512B load.
    const float4* row4 = reinterpret_cast<const float4*>(seq + (size_t)warp * IN_FT);
    float4 v = row4[lane];

    float acc = 0.0f;
    #pragma unroll
    for (int src = 0; src < 32; src++) {
        float a0 = __shfl_sync(0xffffffffu, v.x, src);
        float a1 = __shfl_sync(0xffffffffu, v.y, src);
        float a2 = __shfl_sync(0xffffffffu, v.z, src);
        float a3 = __shfl_sync(0xffffffffu, v.w, src);
        int k = src * 4;
        acc = fmaf(a0, Wsm[(k + 0) * OUT_FT + lane], acc);
        acc = fmaf(a1, Wsm[(k + 1) * OUT_FT + lane], acc);
        acc = fmaf(a2, Wsm[(k + 2) * OUT_FT + lane], acc);
        acc = fmaf(a3, Wsm[(k + 3) * OUT_FT + lane], acc);
    }
    g_support[(size_t)warp * OUT_FT + lane] = acc;
}

// ---------------------------------------------------------------------------
// Kernel 2: COO SpMM scatter. 8 threads per edge; each thread gathers a
// float4 (16 B) of support[col] (coalesced 128 B per edge) and does 4
// atomicAdds into out[row]. support/out both fit in L2.
// Edge indices are int32 (JAX x64-disabled downcasts the requested int64).
// ---------------------------------------------------------------------------
__global__ void gcn_spmm_kernel(const int*   __restrict__ erow,
                                const int*   __restrict__ ecol,
                                const float* __restrict__ eval,
                                float*       __restrict__ out) {
    long long tid = (long long)blockIdx.x * blockDim.x + threadIdx.x;
    long long e = tid >> 3;
    int g = (int)(tid & 7);
    if (e >= N_EDGES) return;

    int r = erow[e];
    int c = ecol[e];
    float v = eval[e];

    const float4* s4 = reinterpret_cast<const float4*>(g_support + (size_t)c * OUT_FT);
    float4 s = s4[g];

    float* o = out + (size_t)r * OUT_FT + g * 4;
    atomicAdd(o + 0, v * s.x);
    atomicAdd(o + 1, v * s.y);
    atomicAdd(o + 2, v * s.z);
    atomicAdd(o + 3, v * s.w);
}

// ---------------------------------------------------------------------------
// Kernel 3: in-place ReLU, float4-vectorized (3.2M elems, divisible by 4).
// ---------------------------------------------------------------------------
__global__ void gcn_relu_kernel(float* __restrict__ out) {
    int i = blockIdx.x * blockDim.x + threadIdx.x;
    const int n4 = (N_NODES * OUT_FT) / 4;
    if (i < n4) {
        float4* p = reinterpret_cast<float4*>(out);
        float4 x = p[i];
        x.x = fmaxf(x.x, 0.0f);
        x.y = fmaxf(x.y, 0.0f);
        x.z = fmaxf(x.z, 0.0f);
        x.w = fmaxf(x.w, 0.0f);
        p[i] = x;
    }
}

extern "C" void kernel_launch(void* const* d_in, const int* in_sizes, int n_in,
                              void* d_out, int out_size) {
    const float* seq  = (const float*)d_in[0];
    const float* W    = (const float*)d_in[1];
    const int*   erow = (const int*)d_in[2];
    const int*   ecol = (const int*)d_in[3];
    const float* eval = (const float*)d_in[4];
    float* out = (float*)d_out;

    // d_out is poisoned; the scatter accumulates, so zero it first.
    cudaMemsetAsync(out, 0, (size_t)out_size * sizeof(float));

    // GEMM: one warp per node, 8 warps per block.
    {
        int threads = 256;
        int warps_per_block = threads / 32;
        int blocks = (N_NODES + warps_per_block - 1) / warps_per_block;
        gcn_gemm_kernel<<<blocks, threads>>>(seq, W);
    }

    // SpMM: 8 threads per edge.
    {
        long long total = (long long)N_EDGES * 8;
        int threads = 256;
        int blocks = (int)((total + threads - 1) / threads);
        gcn_spmm_kernel<<<blocks, threads>>>(erow, ecol, eval, out);
    }

    // ReLU
    {
        int n4 = (N_NODES * OUT_FT) / 4;
        int threads = 256;
        int blocks = (n4 + threads - 1) / threads;
        gcn_relu_kernel<<<blocks, threads>>>(out);
    }
}

// round 4
// speedup vs baseline: 1.4113x; 1.4113x over previous
#include <cuda_runtime.h>
#include <cuda_bf16.h>

#define N_NODES 100000
#define N_EDGES 1600000
#define IN_FT   128
#define OUT_FT  32

#define TILE_NODES 64
#define SEQ_STRIDE 132   // 128 + 4 pad: bank = (4n + k) & 31, conflict-free

// Scratch for the dense projection result (12.8 MB). Device global: no allocs.
__device__ float g_support[(size_t)N_NODES * OUT_FT];

// ---------------------------------------------------------------------------
// Kernel 1: support = seq @ W, register-blocked smem-tiled.
// Block = 256 threads, 64 nodes. Thread (n_local = tid>>2, colgrp = tid&3)
// computes 8 output cols for one node -> 8 independent accumulators.
// Also zero-initializes its slice of `out` (replaces memset; out is
// accumulated by the SpMM atomics afterwards).
// ---------------------------------------------------------------------------
__global__ __launch_bounds__(256) void gcn_gemm_kernel(
        const float* __restrict__ seq,
        const float* __restrict__ W,
        float* __restrict__ out) {
    __shared__ float ssm[TILE_NODES * SEQ_STRIDE];   // ~33.8 KB
    __shared__ float Wsm[IN_FT * OUT_FT];            // 16 KB

    const int tid = threadIdx.x;
    const int node_base = blockIdx.x * TILE_NODES;

    // Load W (4096 floats) coalesced.
    #pragma unroll
    for (int i = 0; i < (IN_FT * OUT_FT) / 256; i++)
        Wsm[tid + i * 256] = W[tid + i * 256];

    // Load seq tile: 64 rows x 128 floats = 2048 float4, 8 per thread.
    for (int idx = tid; idx < TILE_NODES * (IN_FT / 4); idx += 256) {
        int row  = idx >> 5;          // 0..63
        int col4 = idx & 31;          // 0..31 (float4 index)
        int node = node_base + row;
        if (node < N_NODES) {
            float4 v = reinterpret_cast<const float4*>(seq)[(size_t)node * (IN_FT / 4) + col4];
            *reinterpret_cast<float4*>(&ssm[row * SEQ_STRIDE + col4 * 4]) = v;
        }
    }
    __syncthreads();

    const int n_local = tid >> 2;         // 0..63
    const int j0      = (tid & 3) * 8;    // 0,8,16,24
    const int node    = node_base + n_local;

    float acc[8] = {0.f, 0.f, 0.f, 0.f, 0.f, 0.f, 0.f, 0.f};

    const float* srow = &ssm[n_local * SEQ_STRIDE];
    #pragma unroll
    for (int k4 = 0; k4 < IN_FT / 4; k4++) {
        float4 a4 = *reinterpret_cast<const float4*>(&srow[k4 * 4]);
        float a[4] = {a4.x, a4.y, a4.z, a4.w};
        #pragma unroll
        for (int kk = 0; kk < 4; kk++) {
            int k = k4 * 4 + kk;
            float4 w0 = *reinterpret_cast<const float4*>(&Wsm[k * OUT_FT + j0]);
            float4 w1 = *reinterpret_cast<const float4*>(&Wsm[k * OUT_FT + j0 + 4]);
            acc[0] = fmaf(a[kk], w0.x, acc[0]);
            acc[1] = fmaf(a[kk], w0.y, acc[1]);
            acc[2] = fmaf(a[kk], w0.z, acc[2]);
            acc[3] = fmaf(a[kk], w0.w, acc[3]);
            acc[4] = fmaf(a[kk], w1.x, acc[4]);
            acc[5] = fmaf(a[kk], w1.y, acc[5]);
            acc[6] = fmaf(a[kk], w1.z, acc[6]);
            acc[7] = fmaf(a[kk], w1.w, acc[7]);
        }
    }

    if (node < N_NODES) {
        float4* dst = reinterpret_cast<float4*>(&g_support[(size_t)node * OUT_FT + j0]);
        dst[0] = make_float4(acc[0], acc[1], acc[2], acc[3]);
        dst[1] = make_float4(acc[4], acc[5], acc[6], acc[7]);
        // Zero-init out slice (replaces cudaMemsetAsync).
        float4* oz = reinterpret_cast<float4*>(&out[(size_t)node * OUT_FT + j0]);
        oz[0] = make_float4(0.f, 0.f, 0.f, 0.f);
        oz[1] = make_float4(0.f, 0.f, 0.f, 0.f);
    }
}

// ---------------------------------------------------------------------------
// Kernel 2: COO SpMM scatter. 4 threads per edge; each thread gathers
// 8 floats (2x float4, coalesced 128B per edge) and issues 2 vectorized
// red.global.add.v4.f32 (sm_90+) -> 4x fewer atomic address-ops than
// scalar atomicAdd. support/out both stay L2-resident.
// ---------------------------------------------------------------------------
__global__ __launch_bounds__(256) void gcn_spmm_kernel(
        const int*   __restrict__ erow,
        const int*   __restrict__ ecol,
        const float* __restrict__ eval,
        float*       __restrict__ out) {
    long long tid = (long long)blockIdx.x * blockDim.x + threadIdx.x;
    long long e = tid >> 2;
    int g = (int)(tid & 3);           // 8-float chunk id
    if (e >= N_EDGES) return;

    int r = erow[e];
    int c = ecol[e];
    float v = eval[e];

    const float4* s4 = reinterpret_cast<const float4*>(g_support + (size_t)c * OUT_FT + g * 8);
    float4 s0 = s4[0];
    float4 s1 = s4[1];

    float* o = out + (size_t)r * OUT_FT + g * 8;
    asm volatile("red.global.add.v4.f32 [%0], {%1, %2, %3, %4};"
                 :: "l"(o), "f"(v * s0.x), "f"(v * s0.y), "f"(v * s0.z), "f"(v * s0.w)
                 : "memory");
    asm volatile("red.global.add.v4.f32 [%0], {%1, %2, %3, %4};"
                 :: "l"(o + 4), "f"(v * s1.x), "f"(v * s1.y), "f"(v * s1.z), "f"(v * s1.w)
                 : "memory");
}

// ---------------------------------------------------------------------------
// Kernel 3: in-place ReLU, float4-vectorized (3.2M elems, divisible by 4).
// ---------------------------------------------------------------------------
__global__ __launch_bounds__(256) void gcn_relu_kernel(float* __restrict__ out) {
    int i = blockIdx.x * blockDim.x + threadIdx.x;
    const int n4 = (N_NODES * OUT_FT) / 4;
    if (i < n4) {
        float4* p = reinterpret_cast<float4*>(out);
        float4 x = p[i];
        x.x = fmaxf(x.x, 0.0f);
        x.y = fmaxf(x.y, 0.0f);
        x.z = fmaxf(x.z, 0.0f);
        x.w = fmaxf(x.w, 0.0f);
        p[i] = x;
    }
}

extern "C" void kernel_launch(void* const* d_in, const int* in_sizes, int n_in,
                              void* d_out, int out_size) {
    const float* seq  = (const float*)d_in[0];
    const float* W    = (const float*)d_in[1];
    const int*   erow = (const int*)d_in[2];
    const int*   ecol = (const int*)d_in[3];
    const float* eval = (const float*)d_in[4];
    float* out = (float*)d_out;

    // GEMM + zero-init of out.
    {
        int blocks = (N_NODES + TILE_NODES - 1) / TILE_NODES;   // 1563
        gcn_gemm_kernel<<<blocks, 256>>>(seq, W, out);
    }

    // SpMM: 4 threads per edge.
    {
        long long total = (long long)N_EDGES * 4;
        int blocks = (int)((total + 255) / 256);                 // 25000
        gcn_spmm_kernel<<<blocks, 256>>>(erow, ecol, eval, out);
    }

    // ReLU
    {
        int n4 = (N_NODES * OUT_FT) / 4;
        gcn_relu_kernel<<<(n4 + 255) / 256, 256>>>(out);
    }
}

// round 6
// speedup vs baseline: 2.2972x; 1.6278x over previous
#include <cuda_runtime.h>
#include <cuda_bf16.h>

#define N_NODES 100000
#define N_EDGES 1600000
#define IN_FT   128
#define OUT_FT  32

#define TILE_NODES 256
#define KTILE      32          // k per phase (8 float4)
#define ROW_F4     9           // 8 float4 + 1 pad -> conflict-free LDS.128

// Scratch for the dense projection result (12.8 MB). Device global: no allocs.
__device__ float g_support[(size_t)N_NODES * OUT_FT];

// ---------------------------------------------------------------------------
// Kernel 1: support = seq @ W. Register-tiled: 256 threads, 256 nodes/block.
// Thread (n_slot = tid>>2, colgrp = tid&3) computes 4 nodes
// (n_slot + 64*i) x 8 cols -> 32 accumulators. K split into 4 phases of 32.
// Also zero-inits its slice of `out` (SpMM accumulates into it afterwards).
// ---------------------------------------------------------------------------
__global__ __launch_bounds__(256, 3) void gcn_gemm_kernel(
        const float* __restrict__ seq,
        const float* __restrict__ W,
        float* __restrict__ out) {
    __shared__ float4 ssm[TILE_NODES * ROW_F4];   // 36 KB
    __shared__ float  Wsm[KTILE * OUT_FT];        // 4 KB

    const int tid = threadIdx.x;
    const int node_base = blockIdx.x * TILE_NODES;
    const int n_slot = tid >> 2;          // 0..63
    const int j0     = (tid & 3) * 8;     // 0,8,16,24

    float acc[4][8];
    #pragma unroll
    for (int i = 0; i < 4; i++)
        #pragma unroll
        for (int j = 0; j < 8; j++) acc[i][j] = 0.f;

    const float4* seq4 = reinterpret_cast<const float4*>(seq);

    for (int kp = 0; kp < IN_FT / KTILE; kp++) {
        __syncthreads();   // protect smem reuse across phases

        // Stage W slice: 1024 floats = 256 float4, one per thread.
        reinterpret_cast<float4*>(Wsm)[tid] =
            reinterpret_cast<const float4*>(W)[kp * (KTILE * OUT_FT / 4) + tid];

        // Stage seq tile: 256 rows x 8 float4 = 2048 float4, 8 per thread.
        #pragma unroll
        for (int t = 0; t < 8; t++) {
            int idx = tid + t * 256;
            int row = idx >> 3;
            int k4  = idx & 7;
            int node = node_base + row;
            float4 v = make_float4(0.f, 0.f, 0.f, 0.f);
            if (node < N_NODES)
                v = seq4[(size_t)node * (IN_FT / 4) + kp * 8 + k4];
            ssm[row * ROW_F4 + k4] = v;
        }
        __syncthreads();

        #pragma unroll 2
        for (int k4 = 0; k4 < KTILE / 4; k4++) {
            float4 a0 = ssm[(n_slot      ) * ROW_F4 + k4];
            float4 a1 = ssm[(n_slot +  64) * ROW_F4 + k4];
            float4 a2 = ssm[(n_slot + 128) * ROW_F4 + k4];
            float4 a3 = ssm[(n_slot + 192) * ROW_F4 + k4];
            float a[4][4] = {{a0.x, a0.y, a0.z, a0.w},
                             {a1.x, a1.y, a1.z, a1.w},
                             {a2.x, a2.y, a2.z, a2.w},
                             {a3.x, a3.y, a3.z, a3.w}};
            #pragma unroll
            for (int kk = 0; kk < 4; kk++) {
                int k = k4 * 4 + kk;
                float4 w0 = *reinterpret_cast<const float4*>(&Wsm[k * OUT_FT + j0]);
                float4 w1 = *reinterpret_cast<const float4*>(&Wsm[k * OUT_FT + j0 + 4]);
                #pragma unroll
                for (int i = 0; i < 4; i++) {
                    acc[i][0] = fmaf(a[i][kk], w0.x, acc[i][0]);
                    acc[i][1] = fmaf(a[i][kk], w0.y, acc[i][1]);
                    acc[i][2] = fmaf(a[i][kk], w0.z, acc[i][2]);
                    acc[i][3] = fmaf(a[i][kk], w0.w, acc[i][3]);
                    acc[i][4] = fmaf(a[i][kk], w1.x, acc[i][4]);
                    acc[i][5] = fmaf(a[i][kk], w1.y, acc[i][5]);
                    acc[i][6] = fmaf(a[i][kk], w1.z, acc[i][6]);
                    acc[i][7] = fmaf(a[i][kk], w1.w, acc[i][7]);
                }
            }
        }
    }

    #pragma unroll
    for (int i = 0; i < 4; i++) {
        int node = node_base + n_slot + 64 * i;
        if (node < N_NODES) {
            float4* dst = reinterpret_cast<float4*>(&g_support[(size_t)node * OUT_FT + j0]);
            dst[0] = make_float4(acc[i][0], acc[i][1], acc[i][2], acc[i][3]);
            dst[1] = make_float4(acc[i][4], acc[i][5], acc[i][6], acc[i][7]);
            // Zero-init out slice (replaces cudaMemsetAsync).
            float4* oz = reinterpret_cast<float4*>(&out[(size_t)node * OUT_FT + j0]);
            oz[0] = make_float4(0.f, 0.f, 0.f, 0.f);
            oz[1] = make_float4(0.f, 0.f, 0.f, 0.f);
        }
    }
}

// ---------------------------------------------------------------------------
// Kernel 2: COO SpMM scatter. 4 threads per edge; each thread gathers
// 8 floats (2x float4, coalesced 128B per edge) and issues 2 vectorized
// red.global.add.v4.f32 -> 4x fewer atomic address-ops than scalar atomics.
// support/out both stay L2-resident.
// ---------------------------------------------------------------------------
__global__ __launch_bounds__(256) void gcn_spmm_kernel(
        const int*   __restrict__ erow,
        const int*   __restrict__ ecol,
        const float* __restrict__ eval,
        float*       __restrict__ out) {
    long long tid = (long long)blockIdx.x * blockDim.x + threadIdx.x;
    long long e = tid >> 2;
    int g = (int)(tid & 3);
    if (e >= N_EDGES) return;

    int r = erow[e];
    int c = ecol[e];
    float v = eval[e];

    const float4* s4 = reinterpret_cast<const float4*>(g_support + (size_t)c * OUT_FT + g * 8);
    float4 s0 = s4[0];
    float4 s1 = s4[1];

    float* o = out + (size_t)r * OUT_FT + g * 8;
    asm volatile("red.global.add.v4.f32 [%0], {%1, %2, %3, %4};"
                 :: "l"(o), "f"(v * s0.x), "f"(v * s0.y), "f"(v * s0.z), "f"(v * s0.w)
                 : "memory");
    asm volatile("red.global.add.v4.f32 [%0], {%1, %2, %3, %4};"
                 :: "l"(o + 4), "f"(v * s1.x), "f"(v * s1.y), "f"(v * s1.z), "f"(v * s1.w)
                 : "memory");
}

// ---------------------------------------------------------------------------
// Kernel 3: in-place ReLU, float4-vectorized (3.2M elems, divisible by 4).
// ---------------------------------------------------------------------------
__global__ __launch_bounds__(256) void gcn_relu_kernel(float* __restrict__ out) {
    int i = blockIdx.x * blockDim.x + threadIdx.x;
    const int n4 = (N_NODES * OUT_FT) / 4;
    if (i < n4) {
        float4* p = reinterpret_cast<float4*>(out);
        float4 x = p[i];
        x.x = fmaxf(x.x, 0.0f);
        x.y = fmaxf(x.y, 0.0f);
        x.z = fmaxf(x.z, 0.0f);
        x.w = fmaxf(x.w, 0.0f);
        p[i] = x;
    }
}

extern "C" void kernel_launch(void* const* d_in, const int* in_sizes, int n_in,
                              void* d_out, int out_size) {
    const float* seq  = (const float*)d_in[0];
    const float* W    = (const float*)d_in[1];
    const int*   erow = (const int*)d_in[2];
    const int*   ecol = (const int*)d_in[3];
    const float* eval = (const float*)d_in[4];
    float* out = (float*)d_out;

    // GEMM + zero-init of out.
    {
        int blocks = (N_NODES + TILE_NODES - 1) / TILE_NODES;   // 391
        gcn_gemm_kernel<<<blocks, 256>>>(seq, W, out);
    }

    // SpMM: 4 threads per edge.
    {
        long long total = (long long)N_EDGES * 4;
        int blocks = (int)((total + 255) / 256);                 // 25000
        gcn_spmm_kernel<<<blocks, 256>>>(erow, ecol, eval, out);
    }

    // ReLU
    {
        int n4 = (N_NODES * OUT_FT) / 4;
        gcn_relu_kernel<<<(n4 + 255) / 256, 256>>>(out);
    }
}